// round 10
// baseline (speedup 1.0000x reference)
#include <cuda_runtime.h>
#include <cuda_fp16.h>
#include <cstdint>
#include <cstddef>

// ---------------- problem constants ----------------
#define BATCH 8
#define SEQ   1025
#define CH    3200
#define NH    25
#define HD    128
#define MROWS (BATCH*CH > 0 ? BATCH*SEQ : 0)   // 8200
#define EPS   1e-6f
#define LOG2E 1.4426950408889634f

// ---------------- device scratch (no allocation allowed) ----------------
__device__ __half g_xh  [MROWS*CH];      // fp16 x
__device__ __half g_wqkvT[3*CH*CH];      // fp16, TRANSPOSED qkv weights [3C, C]
__device__ __half g_wprojT[CH*CH];       // fp16, TRANSPOSED proj weights [C, C]
__device__ __half g_qh  [MROWS*CH];      // fp16 q (pre-norm -> normalized in place)
__device__ __half g_kh  [MROWS*CH];      // fp16 k (pre-norm -> normalized in place)
__device__ __half g_vh  [MROWS*CH];      // fp16 v
__device__ __half g_o   [MROWS*CH];      // attention output (fp16 for proj GEMM)

// ---------------- PTX helpers ----------------
__device__ __forceinline__ uint32_t smem_u32(const void* p) {
    uint32_t a;
    asm("{ .reg .u64 t; cvta.to.shared.u64 t, %1; cvt.u32.u64 %0, t; }" : "=r"(a) : "l"(p));
    return a;
}

__device__ __forceinline__ void cp_async16(uint32_t smem_addr, const void* gptr, int srcBytes) {
    asm volatile("cp.async.cg.shared.global [%0], [%1], 16, %2;\n"
                 :: "r"(smem_addr), "l"(gptr), "r"(srcBytes) : "memory");
}
__device__ __forceinline__ void cp_async16u(uint32_t smem_addr, const void* gptr) {
    asm volatile("cp.async.cg.shared.global [%0], [%1], 16;\n"
                 :: "r"(smem_addr), "l"(gptr) : "memory");
}
__device__ __forceinline__ void cp_commit() {
    asm volatile("cp.async.commit_group;\n" ::: "memory");
}
__device__ __forceinline__ void cp_wait1() {
    asm volatile("cp.async.wait_group 1;\n" ::: "memory");
}

__device__ __forceinline__ void ldsm_x4(uint32_t r[4], uint32_t addr) {
    asm volatile("ldmatrix.sync.aligned.m8n8.x4.shared.b16 {%0,%1,%2,%3}, [%4];"
                 : "=r"(r[0]), "=r"(r[1]), "=r"(r[2]), "=r"(r[3]) : "r"(addr));
}
__device__ __forceinline__ void ldsm_x4t(uint32_t r[4], uint32_t addr) {
    asm volatile("ldmatrix.sync.aligned.m8n8.x4.trans.shared.b16 {%0,%1,%2,%3}, [%4];"
                 : "=r"(r[0]), "=r"(r[1]), "=r"(r[2]), "=r"(r[3]) : "r"(addr));
}
__device__ __forceinline__ void ldsm_x2t(uint32_t r[2], uint32_t addr) {
    asm volatile("ldmatrix.sync.aligned.m8n8.x2.trans.shared.b16 {%0,%1}, [%2];"
                 : "=r"(r[0]), "=r"(r[1]) : "r"(addr));
}

__device__ __forceinline__ void mma16816(float c[4], const uint32_t a[4],
                                         uint32_t b0, uint32_t b1) {
    asm volatile(
        "mma.sync.aligned.m16n8k16.row.col.f32.f16.f16.f32 "
        "{%0,%1,%2,%3}, {%4,%5,%6,%7}, {%8,%9}, {%0,%1,%2,%3};\n"
        : "+f"(c[0]), "+f"(c[1]), "+f"(c[2]), "+f"(c[3])
        : "r"(a[0]), "r"(a[1]), "r"(a[2]), "r"(a[3]), "r"(b0), "r"(b1));
}

__device__ __forceinline__ uint32_t ex2_h2(uint32_t x) {
    uint32_t r;
    asm volatile("ex2.approx.f16x2 %0, %1;" : "=r"(r) : "r"(x));
    return r;
}

__device__ __forceinline__ uint32_t pack_h2(float lo, float hi) {
    __half2 h = __floats2half2_rn(lo, hi);
    return *reinterpret_cast<uint32_t*>(&h);
}

#define SWZ(b) ((b) ^ (((b) >> 3) & 0x70))

// ---------------- fused prep: f2h(x) + transpose both weight matrices ----------------
// grid.x partition: [0, 25625) f2h blocks; [25625, 25625+40000) transpose blocks
#define F2H_NBLK 25625          // MROWS*CH/4/256 exactly
#define TR_QKV_NX 300           // 3*CH/32
#define TR_NX     400           // + CH/32
__global__ void prep_kernel(const float4* __restrict__ x, uint2* __restrict__ xh,
                            const float* __restrict__ w1, __half* __restrict__ o1,
                            const float* __restrict__ w2, __half* __restrict__ o2)
{
    __shared__ float t[32][33];
    const int tid = threadIdx.x;
    if (blockIdx.x < F2H_NBLK) {
        int i = blockIdx.x * 256 + tid;            // exact multiple, no bounds check
        float4 v = x[i];
        __half2 lo = __floats2half2_rn(v.x, v.y);
        __half2 hi = __floats2half2_rn(v.z, v.w);
        uint2 u;
        u.x = *reinterpret_cast<uint32_t*>(&lo);
        u.y = *reinterpret_cast<uint32_t*>(&hi);
        xh[i] = u;
        return;
    }
    int bid = blockIdx.x - F2H_NBLK;
    int bx = bid % TR_NX, by = bid / TR_NX;
    const float* in;
    __half* out;
    int N;
    if (bx < TR_QKV_NX) { in = w1; out = o1; N = 3 * CH; }
    else                { in = w2; out = o2; N = CH; bx -= TR_QKV_NX; }
    const int nb = bx * 32, kb = by * 32;
    const int tx = tid & 31, ty = tid >> 5;
    #pragma unroll
    for (int j = 0; j < 32; j += 8)
        t[ty + j][tx] = in[(size_t)(kb + ty + j) * N + nb + tx];
    __syncthreads();
    #pragma unroll
    for (int j = 0; j < 32; j += 8)
        out[(size_t)(nb + ty + j) * CH + kb + tx] = __float2half_rn(t[tx][ty + j]);
}

// ---------------- fp16 GEMM: 128x128 CTA tile, 4 warps x (64x64), 2 CTA/SM ----------------
#define HSTG 32768
#define HG_SMEM (3*HSTG)

__global__ void __launch_bounds__(128, 2) hgemm(
    const __half* __restrict__ A, const __half* __restrict__ BT,
    const float* __restrict__ bias,
    __half* __restrict__ oq, __half* __restrict__ ok, __half* __restrict__ ov,
    float* __restrict__ od,
    int Mdim, int split)
{
    extern __shared__ char smg[];
    const uint32_t sb = smem_u32(smg);
    const int tid  = threadIdx.x;
    const int lane = tid & 31;
    const int wid  = tid >> 5;          // 0..3
    const int g    = lane >> 2;
    const int q    = lane & 3;
    const int m0   = blockIdx.x * 128;
    const int n0   = blockIdx.y * 128;
    const int wm   = (wid & 1) * 64;
    const int wn   = (wid >> 1) * 64;
    const int nk   = CH / 64;           // 50
    const bool fullM = (m0 + 128 <= Mdim);

    float c[4][8][4];
    #pragma unroll
    for (int i = 0; i < 4; i++)
        #pragma unroll
        for (int j = 0; j < 8; j++)
            #pragma unroll
            for (int t = 0; t < 4; t++) c[i][j][t] = 0.f;

    const int ldR = tid >> 3, ldC = tid & 7;

    auto stage = [&](int ts) {
        const int k0 = ts * 64;
        const uint32_t bufb = sb + (ts % 3) * HSTG;
        if (fullM) {
            #pragma unroll
            for (int i = 0; i < 8; i++) {
                int r = ldR + (i << 4);
                const __half* src = A + (size_t)(m0 + r) * CH + k0 + ldC * 8;
                uint32_t byte = (r << 7) + (ldC << 4);
                cp_async16u(bufb + SWZ(byte), src);
            }
        } else {
            #pragma unroll
            for (int i = 0; i < 8; i++) {
                int r = ldR + (i << 4);
                int grow = m0 + r;
                const __half* src = A + (size_t)(grow < Mdim ? grow : 0) * CH + k0 + ldC * 8;
                uint32_t byte = (r << 7) + (ldC << 4);
                cp_async16(bufb + SWZ(byte), src, grow < Mdim ? 16 : 0);
            }
        }
        #pragma unroll
        for (int i = 0; i < 8; i++) {
            int r = ldR + (i << 4);
            const __half* src = BT + (size_t)(n0 + r) * CH + k0 + ldC * 8;
            uint32_t byte = (r << 7) + (ldC << 4);
            cp_async16u(bufb + 16384 + SWZ(byte), src);
        }
        cp_commit();
    };

    stage(0);
    stage(1);

    const int aRow = wm + (lane & 15);
    const int aKb  = (lane >> 4) << 4;
    const int bRow = wn + (lane & 7) + ((lane & 16) >> 1);
    const int bKb  = (lane & 8) << 1;

    for (int kt = 0; kt < nk; kt++) {
        cp_wait1();
        __syncthreads();
        if (kt + 2 < nk) stage(kt + 2);
        else cp_commit();

        const uint32_t Ab = sb + (kt % 3) * HSTG;
        const uint32_t Bb = Ab + 16384;
        #pragma unroll
        for (int ks = 0; ks < 4; ks++) {
            uint32_t a[4][4], b[4][4];
            #pragma unroll
            for (int i = 0; i < 4; i++) {
                uint32_t byte = ((aRow + i * 16) << 7) + ks * 32 + aKb;
                ldsm_x4(a[i], Ab + SWZ(byte));
            }
            #pragma unroll
            for (int j = 0; j < 4; j++) {
                uint32_t byte = ((bRow + j * 16) << 7) + ks * 32 + bKb;
                ldsm_x4(b[j], Bb + SWZ(byte));
            }
            #pragma unroll
            for (int i = 0; i < 4; i++)
                #pragma unroll
                for (int j = 0; j < 4; j++) {
                    mma16816(c[i][2 * j],     a[i], b[j][0], b[j][1]);
                    mma16816(c[i][2 * j + 1], a[i], b[j][2], b[j][3]);
                }
        }
    }

    // epilogue
    if (!split) {
        #pragma unroll
        for (int i = 0; i < 4; i++) {
            int r0 = m0 + wm + i * 16 + g;
            #pragma unroll
            for (int j = 0; j < 8; j++) {
                int col = n0 + wn + j * 8 + 2 * q;
                float b0 = bias[col], b1 = bias[col + 1];
                if (r0 < Mdim) {
                    float* d = od + (size_t)r0 * CH + col;
                    d[0] = c[i][j][0] + b0;
                    d[1] = c[i][j][1] + b1;
                }
                if (r0 + 8 < Mdim) {
                    float* d = od + (size_t)(r0 + 8) * CH + col;
                    d[0] = c[i][j][2] + b0;
                    d[1] = c[i][j][3] + b1;
                }
            }
        }
    } else {
        int sel = n0 / CH;
        int cs  = sel * CH;
        __half* outp = (sel == 0) ? oq : (sel == 1 ? ok : ov);
        #pragma unroll
        for (int i = 0; i < 4; i++) {
            int r0 = m0 + wm + i * 16 + g;
            #pragma unroll
            for (int j = 0; j < 8; j++) {
                int col = n0 + wn + j * 8 + 2 * q;
                float b0 = bias[col], b1 = bias[col + 1];
                if (r0 < Mdim) {
                    __half2* d = (__half2*)(outp + (size_t)r0 * CH + (col - cs));
                    *d = __floats2half2_rn(c[i][j][0] + b0, c[i][j][1] + b1);
                }
                if (r0 + 8 < Mdim) {
                    __half2* d = (__half2*)(outp + (size_t)(r0 + 8) * CH + (col - cs));
                    *d = __floats2half2_rn(c[i][j][2] + b0, c[i][j][3] + b1);
                }
            }
        }
    }
}

// ---------------- RMSNorm (fp16, in place, uint4 loads, register-cached) ----------------
__device__ __forceinline__ float sumsq8(uint4 u) {
    float2 a = __half22float2(*reinterpret_cast<__half2*>(&u.x));
    float2 b = __half22float2(*reinterpret_cast<__half2*>(&u.y));
    float2 c = __half22float2(*reinterpret_cast<__half2*>(&u.z));
    float2 d = __half22float2(*reinterpret_cast<__half2*>(&u.w));
    return a.x * a.x + a.y * a.y + b.x * b.x + b.y * b.y +
           c.x * c.x + c.y * c.y + d.x * d.x + d.y * d.y;
}
__device__ __forceinline__ uint4 scale8(uint4 u, float4 w0, float4 w1, float rms) {
    float2 a = __half22float2(*reinterpret_cast<__half2*>(&u.x));
    float2 b = __half22float2(*reinterpret_cast<__half2*>(&u.y));
    float2 c = __half22float2(*reinterpret_cast<__half2*>(&u.z));
    float2 d = __half22float2(*reinterpret_cast<__half2*>(&u.w));
    __half2 h0 = __floats2half2_rn(a.x * rms * w0.x, a.y * rms * w0.y);
    __half2 h1 = __floats2half2_rn(b.x * rms * w0.z, b.y * rms * w0.w);
    __half2 h2 = __floats2half2_rn(c.x * rms * w1.x, c.y * rms * w1.y);
    __half2 h3 = __floats2half2_rn(d.x * rms * w1.z, d.y * rms * w1.w);
    uint4 r;
    r.x = *reinterpret_cast<uint32_t*>(&h0);
    r.y = *reinterpret_cast<uint32_t*>(&h1);
    r.z = *reinterpret_cast<uint32_t*>(&h2);
    r.w = *reinterpret_cast<uint32_t*>(&h3);
    return r;
}

__global__ void rmsnorm_kernel(__half* __restrict__ qbuf, __half* __restrict__ kbuf,
                               const float* __restrict__ qw, const float* __restrict__ kw)
{
    __half* buf    = blockIdx.y ? kbuf : qbuf;
    const float* w = blockIdx.y ? kw : qw;
    const float post = blockIdx.y ? 1.f : 0.08838834764831845f;   // q: fold attn scale
    const size_t row = blockIdx.x;
    uint4* p = (uint4*)(buf + row * CH);          // 400 uint4 per row
    const float4* wp = (const float4*)w;
    const int tid = threadIdx.x;                  // 256

    const bool has1 = (tid + 256) < 400;
    uint4 v0 = p[tid];
    uint4 v1;
    if (has1) v1 = p[tid + 256];

    float ss = sumsq8(v0) + (has1 ? sumsq8(v1) : 0.f);
    __shared__ float red[8];
    #pragma unroll
    for (int off = 16; off > 0; off >>= 1) ss += __shfl_xor_sync(0xffffffffu, ss, off);
    if ((tid & 31) == 0) red[tid >> 5] = ss;
    __syncthreads();
    float tot = 0.f;
    #pragma unroll
    for (int i = 0; i < 8; i++) tot += red[i];
    const float rms = rsqrtf(tot * (1.f / CH) + EPS) * post;

    p[tid] = scale8(v0, wp[2 * tid], wp[2 * tid + 1], rms);
    if (has1) p[tid + 256] = scale8(v1, wp[2 * (tid + 256)], wp[2 * (tid + 256) + 1], rms);
}

// ---------------- flash attention, fp16 mma, register-resident P ----------------
// Main kernel covers q rows [0, 1024): 8 FULL tiles (no q-dim masking).
#define ROWB 272
#define AQ_BYTES (128*ROWB)
#define KV_BYTES (2*64*ROWB)
#define ATTN_SMEM (AQ_BYTES + 2*KV_BYTES)  // 104448

__global__ void __launch_bounds__(256, 2) attn_kernel(
    const __half* __restrict__ Q, const __half* __restrict__ K,
    const __half* __restrict__ V, __half* __restrict__ O)
{
    extern __shared__ char smg[];
    const uint32_t sb = smem_u32(smg);
    const int tid  = threadIdx.x;
    const int lane = tid & 31;
    const int wid  = tid >> 5;
    const int g    = lane >> 2;
    const int q    = lane & 3;
    const int bh   = blockIdx.x;
    const int b    = bh / NH;
    const int h    = bh % NH;
    const int q0   = blockIdx.y * 128;
    const size_t rowBase = (size_t)b * SEQ;
    const int nkt = (SEQ + 63) / 64;     // 17

    for (int i = tid; i < 2048; i += 256) {
        int r = i >> 4, c = i & 15;
        const __half* src = Q + (rowBase + q0 + r) * (size_t)CH + h * HD + c * 8;
        cp_async16u(sb + r * ROWB + c * 16, src);
    }
    cp_commit();

    auto kvstage = [&](int kt) {
        const int k0 = kt * 64;
        const uint32_t bufb = sb + AQ_BYTES + (kt & 1) * KV_BYTES;
        for (int i = tid; i < 1024; i += 256) {
            int r = i >> 4, c = i & 15;
            int krow = k0 + r;
            size_t off = (rowBase + krow) * (size_t)CH + h * HD + c * 8;
            int ok = krow < SEQ ? 16 : 0;
            cp_async16(bufb + r * ROWB + c * 16, K + off, ok);
            cp_async16(bufb + 64 * ROWB + r * ROWB + c * 16, V + off, ok);
        }
        cp_commit();
    };

    kvstage(0);

    if (tid < 128) {
        int buf = tid >> 6, r = tid & 63;
        uint4* p = (uint4*)(smg + AQ_BYTES + buf * KV_BYTES + 64 * ROWB + r * ROWB + 256);
        *p = make_uint4(0x00003c00u, 0u, 0u, 0u);   // halves {1,0,0,0,0,0,0,0}
    }

    float o[17][4];
    #pragma unroll
    for (int j = 0; j < 17; j++)
        #pragma unroll
        for (int t = 0; t < 4; t++) o[j][t] = 0.f;
    float mstat0 = -1e30f, mstat1 = -1e30f;

    const uint32_t aQbase = sb + (wid * 16 + (lane & 15)) * ROWB + ((lane >> 4) << 4);
    const int bRowOff = (lane & 7) + ((lane & 16) >> 1);
    const int bKb     = (lane & 8) << 1;
    const int vRowOff = ((lane >> 3) & 1) * 8 + (lane & 7);
    const int vColOff = (lane >> 4) << 4;

    for (int kt = 0; kt < nkt; kt++) {
        if (kt + 1 < nkt) kvstage(kt + 1);
        else cp_commit();
        cp_wait1();
        __syncthreads();

        const uint32_t Kb = sb + AQ_BYTES + (kt & 1) * KV_BYTES;
        const uint32_t Vb = Kb + 64 * ROWB;

        float s[8][4];
        #pragma unroll
        for (int nt = 0; nt < 8; nt++)
            #pragma unroll
            for (int t = 0; t < 4; t++) s[nt][t] = 0.f;
        #pragma unroll
        for (int kb = 0; kb < 8; kb++) {
            uint32_t a[4];
            ldsm_x4(a, aQbase + kb * 32);
            #pragma unroll
            for (int nt = 0; nt < 4; nt++) {
                uint32_t bf[4];
                ldsm_x4(bf, Kb + (nt * 16 + bRowOff) * ROWB + kb * 32 + bKb);
                mma16816(s[2 * nt],     a, bf[0], bf[1]);
                mma16816(s[2 * nt + 1], a, bf[2], bf[3]);
            }
        }

        const int kvalid = SEQ - kt * 64;
        if (kvalid < 64) {
            #pragma unroll
            for (int nt = 0; nt < 8; nt++) {
                int colb = nt * 8 + 2 * q;
                if (colb >= kvalid)     { s[nt][0] = -1e30f; s[nt][2] = -1e30f; }
                if (colb + 1 >= kvalid) { s[nt][1] = -1e30f; s[nt][3] = -1e30f; }
            }
        }

        float cm0 = -1e30f, cm1 = -1e30f;
        #pragma unroll
        for (int nt = 0; nt < 8; nt++) {
            cm0 = fmaxf(cm0, fmaxf(s[nt][0], s[nt][1]));
            cm1 = fmaxf(cm1, fmaxf(s[nt][2], s[nt][3]));
        }
        cm0 = fmaxf(cm0, __shfl_xor_sync(0xffffffffu, cm0, 1));
        cm0 = fmaxf(cm0, __shfl_xor_sync(0xffffffffu, cm0, 2));
        cm1 = fmaxf(cm1, __shfl_xor_sync(0xffffffffu, cm1, 1));
        cm1 = fmaxf(cm1, __shfl_xor_sync(0xffffffffu, cm1, 2));

        const float mn0 = fmaxf(mstat0, cm0);
        const float mn1 = fmaxf(mstat1, cm1);
        const float al0 = __expf(mstat0 - mn0);
        const float al1 = __expf(mstat1 - mn1);
        mstat0 = mn0; mstat1 = mn1;
        const float cc0 = -mn0 * LOG2E;
        const float cc1 = -mn1 * LOG2E;

        uint32_t ph[8][2];
        #pragma unroll
        for (int nt = 0; nt < 8; nt++) {
            ph[nt][0] = ex2_h2(pack_h2(fmaf(s[nt][0], LOG2E, cc0),
                                       fmaf(s[nt][1], LOG2E, cc0)));
            ph[nt][1] = ex2_h2(pack_h2(fmaf(s[nt][2], LOG2E, cc1),
                                       fmaf(s[nt][3], LOG2E, cc1)));
        }

        if (__float_as_uint(al0) != 0x3f800000u || __float_as_uint(al1) != 0x3f800000u) {
            #pragma unroll
            for (int j = 0; j < 17; j++) {
                o[j][0] *= al0; o[j][1] *= al0;
                o[j][2] *= al1; o[j][3] *= al1;
            }
        }

        #pragma unroll
        for (int m = 0; m < 4; m++) {
            uint32_t a[4] = { ph[2 * m][0], ph[2 * m][1], ph[2 * m + 1][0], ph[2 * m + 1][1] };
            const uint32_t vb = Vb + (m * 16 + vRowOff) * ROWB;
            #pragma unroll
            for (int nb = 0; nb < 8; nb++) {
                uint32_t r[4];
                ldsm_x4t(r, vb + nb * 32 + vColOff);
                mma16816(o[2 * nb],     a, r[0], r[1]);
                mma16816(o[2 * nb + 1], a, r[2], r[3]);
            }
            uint32_t rl[2];
            ldsm_x2t(rl, Vb + (m * 16 + vRowOff) * ROWB + 256);
            mma16816(o[16], a, rl[0], rl[1]);
        }
        __syncthreads();
    }

    const float l0 = __shfl_sync(0xffffffffu, o[16][0], lane & ~3);
    const float l1 = __shfl_sync(0xffffffffu, o[16][2], lane & ~3);
    const float inv0 = 1.f / l0;
    const float inv1 = 1.f / l1;
    const int row0 = q0 + wid * 16 + g;
    #pragma unroll
    for (int j = 0; j < 16; j++) {
        int col = h * HD + j * 8 + 2 * q;
        __half2* d0 = (__half2*)(O + (rowBase + row0) * (size_t)CH + col);
        *d0 = __floats2half2_rn(o[j][0] * inv0, o[j][1] * inv0);
        __half2* d1 = (__half2*)(O + (rowBase + row0 + 8) * (size_t)CH + col);
        *d1 = __floats2half2_rn(o[j][2] * inv1, o[j][3] * inv1);
    }
}

// ---------------- attention tail: the single q row 1024, fp32 scalar path ----------------
// grid: (BATCH*NH) blocks, 256 threads
__global__ void attn_tail(const __half* __restrict__ Q, const __half* __restrict__ K,
                          const __half* __restrict__ V, __half* __restrict__ O)
{
    __shared__ float qs[HD];
    __shared__ float ps[SEQ];
    __shared__ float red[8];
    __shared__ float osum[HD];

    const int bh = blockIdx.x;
    const int b  = bh / NH;
    const int h  = bh % NH;
    const size_t rowBase = (size_t)b * SEQ;
    const int qrow = SEQ - 1;
    const int tid = threadIdx.x;

    if (tid < HD / 2) {
        __half2 v = ((const __half2*)(Q + (rowBase + qrow) * (size_t)CH + h * HD))[tid];
        float2 f = __half22float2(v);
        qs[2 * tid] = f.x; qs[2 * tid + 1] = f.y;
    }
    __syncthreads();

    // scores (q already carries the attn scale from rmsnorm fold)
    float lmax = -1e30f;
    for (int k = tid; k < SEQ; k += 256) {
        const __half2* kp = (const __half2*)(K + (rowBase + k) * (size_t)CH + h * HD);
        float s = 0.f;
        #pragma unroll
        for (int d = 0; d < HD / 2; d++) {
            float2 f = __half22float2(kp[d]);
            s += qs[2 * d] * f.x + qs[2 * d + 1] * f.y;
        }
        ps[k] = s;
        lmax = fmaxf(lmax, s);
    }
    #pragma unroll
    for (int off = 16; off > 0; off >>= 1) lmax = fmaxf(lmax, __shfl_xor_sync(0xffffffffu, lmax, off));
    if ((tid & 31) == 0) red[tid >> 5] = lmax;
    __syncthreads();
    float gmax = red[0];
    #pragma unroll
    for (int i = 1; i < 8; i++) gmax = fmaxf(gmax, red[i]);
    __syncthreads();

    float lsum = 0.f;
    for (int k = tid; k < SEQ; k += 256) {
        float p = __expf(ps[k] - gmax);
        ps[k] = p;
        lsum += p;
    }
    #pragma unroll
    for (int off = 16; off > 0; off >>= 1) lsum += __shfl_xor_sync(0xffffffffu, lsum, off);
    if ((tid & 31) == 0) red[tid >> 5] = lsum;
    __syncthreads();
    float gsum = 0.f;
    #pragma unroll
    for (int i = 0; i < 8; i++) gsum += red[i];

    // output: 2 groups of 128 threads split the keys
    const int d = tid & 127, grp = tid >> 7;
    float acc = 0.f;
    #pragma unroll 4
    for (int k = grp; k < SEQ; k += 2)
        acc += ps[k] * __half2float(V[(rowBase + k) * (size_t)CH + h * HD + d]);
    if (grp == 0) osum[d] = acc;
    __syncthreads();
    if (grp == 1) osum[d] += acc;
    __syncthreads();
    if (tid < HD)
        O[(rowBase + qrow) * (size_t)CH + h * HD + tid] = __float2half_rn(osum[tid] / gsum);
}

// ---------------- launch ----------------
extern "C" void kernel_launch(void* const* d_in, const int* in_sizes, int n_in,
                              void* d_out, int out_size)
{
    const float* x     = (const float*)d_in[0];
    const float* qkvW  = (const float*)d_in[1];
    const float* qkvB  = (const float*)d_in[2];
    const float* qNW   = (const float*)d_in[3];
    const float* kNW   = (const float*)d_in[4];
    const float* projW = (const float*)d_in[5];
    const float* projB = (const float*)d_in[6];
    float* out = (float*)d_out;

    __half *pxh, *pwqT, *pwpT, *pqh, *pkh, *pvh, *po;
    cudaGetSymbolAddress((void**)&pxh,  g_xh);
    cudaGetSymbolAddress((void**)&pwqT, g_wqkvT);
    cudaGetSymbolAddress((void**)&pwpT, g_wprojT);
    cudaGetSymbolAddress((void**)&pqh,  g_qh);
    cudaGetSymbolAddress((void**)&pkh,  g_kh);
    cudaGetSymbolAddress((void**)&pvh,  g_vh);
    cudaGetSymbolAddress((void**)&po,   g_o);

    cudaFuncSetAttribute(hgemm,       cudaFuncAttributeMaxDynamicSharedMemorySize, HG_SMEM);
    cudaFuncSetAttribute(attn_kernel, cudaFuncAttributeMaxDynamicSharedMemorySize, ATTN_SMEM);

    // fused prep: f2h(x) + transposed fp16 weights
    prep_kernel<<<F2H_NBLK + TR_NX * 100, 256>>>((const float4*)x, (uint2*)pxh,
                                                 qkvW, pwqT, projW, pwpT);

    // qkv = x @ W_qkv + b  ->  q,k,v fp16
    hgemm<<<dim3(65, 75), 128, HG_SMEM>>>(pxh, pwqT, qkvB, pqh, pkh, pvh, nullptr, MROWS, 1);
    // RMSNorm in place (q gets attn scale folded)
    rmsnorm_kernel<<<dim3(MROWS, 2), 256>>>(pqh, pkh, qNW, kNW);
    // flash attention: 8 full q-tiles + scalar tail for row 1024
    attn_kernel<<<dim3(BATCH * NH, 8), 256, ATTN_SMEM>>>(pqh, pkh, pvh, po);
    attn_tail<<<BATCH * NH, 256>>>(pqh, pkh, pvh, po);
    // out = attn_out @ W_proj + b (fp32 out)
    hgemm<<<dim3(65, 25), 128, HG_SMEM>>>(po, pwpT, projB, nullptr, nullptr, nullptr, out, MROWS, 0);
}

// round 11
// speedup vs baseline: 1.0903x; 1.0903x over previous
#include <cuda_runtime.h>
#include <cuda_fp16.h>
#include <cstdint>
#include <cstddef>

// ---------------- problem constants ----------------
#define BATCH 8
#define SEQ   1025
#define CH    3200
#define NH    25
#define HD    128
#define MROWS (BATCH*SEQ)   // 8200
#define EPS   1e-6f
#define LOG2E 1.4426950408889634f

// ---------------- device scratch (no allocation allowed) ----------------
__device__ __half g_xh  [MROWS*CH];      // fp16 x
__device__ __half g_wqkvT[3*CH*CH];      // fp16, TRANSPOSED qkv weights [3C, C]
__device__ __half g_wprojT[CH*CH];       // fp16, TRANSPOSED proj weights [C, C]
__device__ __half g_qh  [MROWS*CH];      // fp16 q (pre-norm -> normalized in place)
__device__ __half g_kh  [MROWS*CH];      // fp16 k (pre-norm -> normalized in place)
__device__ __half g_vh  [MROWS*CH];      // fp16 v
__device__ __half g_o   [MROWS*CH];      // attention output (fp16 for proj GEMM)

// ---------------- PTX helpers ----------------
__device__ __forceinline__ uint32_t smem_u32(const void* p) {
    uint32_t a;
    asm("{ .reg .u64 t; cvta.to.shared.u64 t, %1; cvt.u32.u64 %0, t; }" : "=r"(a) : "l"(p));
    return a;
}

__device__ __forceinline__ void cp_async16(uint32_t smem_addr, const void* gptr, int srcBytes) {
    asm volatile("cp.async.cg.shared.global [%0], [%1], 16, %2;\n"
                 :: "r"(smem_addr), "l"(gptr), "r"(srcBytes) : "memory");
}
__device__ __forceinline__ void cp_async16u(uint32_t smem_addr, const void* gptr) {
    asm volatile("cp.async.cg.shared.global [%0], [%1], 16;\n"
                 :: "r"(smem_addr), "l"(gptr) : "memory");
}
__device__ __forceinline__ void cp_commit() {
    asm volatile("cp.async.commit_group;\n" ::: "memory");
}
__device__ __forceinline__ void cp_wait1() {
    asm volatile("cp.async.wait_group 1;\n" ::: "memory");
}

__device__ __forceinline__ void ldsm_x4(uint32_t r[4], uint32_t addr) {
    asm volatile("ldmatrix.sync.aligned.m8n8.x4.shared.b16 {%0,%1,%2,%3}, [%4];"
                 : "=r"(r[0]), "=r"(r[1]), "=r"(r[2]), "=r"(r[3]) : "r"(addr));
}
__device__ __forceinline__ void ldsm_x4t(uint32_t r[4], uint32_t addr) {
    asm volatile("ldmatrix.sync.aligned.m8n8.x4.trans.shared.b16 {%0,%1,%2,%3}, [%4];"
                 : "=r"(r[0]), "=r"(r[1]), "=r"(r[2]), "=r"(r[3]) : "r"(addr));
}
__device__ __forceinline__ void ldsm_x2t(uint32_t r[2], uint32_t addr) {
    asm volatile("ldmatrix.sync.aligned.m8n8.x2.trans.shared.b16 {%0,%1}, [%2];"
                 : "=r"(r[0]), "=r"(r[1]) : "r"(addr));
}

__device__ __forceinline__ void mma16816(float c[4], const uint32_t a[4],
                                         uint32_t b0, uint32_t b1) {
    asm volatile(
        "mma.sync.aligned.m16n8k16.row.col.f32.f16.f16.f32 "
        "{%0,%1,%2,%3}, {%4,%5,%6,%7}, {%8,%9}, {%0,%1,%2,%3};\n"
        : "+f"(c[0]), "+f"(c[1]), "+f"(c[2]), "+f"(c[3])
        : "r"(a[0]), "r"(a[1]), "r"(a[2]), "r"(a[3]), "r"(b0), "r"(b1));
}

__device__ __forceinline__ uint32_t ex2_h2(uint32_t x) {
    uint32_t r;
    asm volatile("ex2.approx.f16x2 %0, %1;" : "=r"(r) : "r"(x));
    return r;
}

__device__ __forceinline__ uint32_t pack_h2(float lo, float hi) {
    __half2 h = __floats2half2_rn(lo, hi);
    return *reinterpret_cast<uint32_t*>(&h);
}

#define SWZ(b) ((b) ^ (((b) >> 3) & 0x70))

// ---------------- prep kernels (round-9 proven versions) ----------------
__global__ void f2h_kernel(const float4* __restrict__ in, uint2* __restrict__ out, int n4) {
    int i = blockIdx.x * blockDim.x + threadIdx.x;
    if (i < n4) {
        float4 v = in[i];
        __half2 lo = __floats2half2_rn(v.x, v.y);
        __half2 hi = __floats2half2_rn(v.z, v.w);
        uint2 u;
        u.x = *reinterpret_cast<uint32_t*>(&lo);
        u.y = *reinterpret_cast<uint32_t*>(&hi);
        out[i] = u;
    }
}

// fused: transpose+convert both weight matrices in one launch.
__global__ void transpose2_h(const float* __restrict__ w1, __half* __restrict__ o1,
                             const float* __restrict__ w2, __half* __restrict__ o2) {
    __shared__ float t[32][33];
    int bx = blockIdx.x;
    const float* in;
    __half* out;
    int N;
    if (bx < 300) { in = w1; out = o1; N = 3 * CH; }
    else          { in = w2; out = o2; N = CH; bx -= 300; }
    const int nb = bx * 32, kb = blockIdx.y * 32;
    const int tx = threadIdx.x, ty = threadIdx.y;
    #pragma unroll
    for (int j = 0; j < 32; j += 8)
        t[ty + j][tx] = in[(size_t)(kb + ty + j) * N + nb + tx];
    __syncthreads();
    #pragma unroll
    for (int j = 0; j < 32; j += 8)
        out[(size_t)(nb + ty + j) * CH + kb + tx] = __float2half_rn(t[tx][ty + j]);
}

// ---------------- fp16 GEMM: 128x128 CTA tile, 4 warps x (64x64), 2 CTA/SM ----------------
#define HSTG 32768
#define HG_SMEM (3*HSTG)

__global__ void __launch_bounds__(128, 2) hgemm(
    const __half* __restrict__ A, const __half* __restrict__ BT,
    const float* __restrict__ bias,
    __half* __restrict__ oq, __half* __restrict__ ok, __half* __restrict__ ov,
    float* __restrict__ od,
    int Mdim, int split)
{
    extern __shared__ char smg[];
    const uint32_t sb = smem_u32(smg);
    const int tid  = threadIdx.x;
    const int lane = tid & 31;
    const int wid  = tid >> 5;          // 0..3
    const int g    = lane >> 2;
    const int q    = lane & 3;
    const int m0   = blockIdx.x * 128;
    const int n0   = blockIdx.y * 128;
    const int wm   = (wid & 1) * 64;
    const int wn   = (wid >> 1) * 64;
    const int nk   = CH / 64;           // 50
    const bool fullM = (m0 + 128 <= Mdim);

    float c[4][8][4];
    #pragma unroll
    for (int i = 0; i < 4; i++)
        #pragma unroll
        for (int j = 0; j < 8; j++)
            #pragma unroll
            for (int t = 0; t < 4; t++) c[i][j][t] = 0.f;

    const int ldR = tid >> 3, ldC = tid & 7;

    auto stage = [&](int ts) {
        const int k0 = ts * 64;
        const uint32_t bufb = sb + (ts % 3) * HSTG;
        if (fullM) {
            #pragma unroll
            for (int i = 0; i < 8; i++) {
                int r = ldR + (i << 4);
                const __half* src = A + (size_t)(m0 + r) * CH + k0 + ldC * 8;
                uint32_t byte = (r << 7) + (ldC << 4);
                cp_async16u(bufb + SWZ(byte), src);
            }
        } else {
            #pragma unroll
            for (int i = 0; i < 8; i++) {
                int r = ldR + (i << 4);
                int grow = m0 + r;
                const __half* src = A + (size_t)(grow < Mdim ? grow : 0) * CH + k0 + ldC * 8;
                uint32_t byte = (r << 7) + (ldC << 4);
                cp_async16(bufb + SWZ(byte), src, grow < Mdim ? 16 : 0);
            }
        }
        #pragma unroll
        for (int i = 0; i < 8; i++) {
            int r = ldR + (i << 4);
            const __half* src = BT + (size_t)(n0 + r) * CH + k0 + ldC * 8;
            uint32_t byte = (r << 7) + (ldC << 4);
            cp_async16u(bufb + 16384 + SWZ(byte), src);
        }
        cp_commit();
    };

    stage(0);
    stage(1);

    const int aRow = wm + (lane & 15);
    const int aKb  = (lane >> 4) << 4;
    const int bRow = wn + (lane & 7) + ((lane & 16) >> 1);
    const int bKb  = (lane & 8) << 1;

    for (int kt = 0; kt < nk; kt++) {
        cp_wait1();
        __syncthreads();
        if (kt + 2 < nk) stage(kt + 2);
        else cp_commit();

        const uint32_t Ab = sb + (kt % 3) * HSTG;
        const uint32_t Bb = Ab + 16384;
        #pragma unroll
        for (int ks = 0; ks < 4; ks++) {
            uint32_t a[4][4], b[4][4];
            #pragma unroll
            for (int i = 0; i < 4; i++) {
                uint32_t byte = ((aRow + i * 16) << 7) + ks * 32 + aKb;
                ldsm_x4(a[i], Ab + SWZ(byte));
            }
            #pragma unroll
            for (int j = 0; j < 4; j++) {
                uint32_t byte = ((bRow + j * 16) << 7) + ks * 32 + bKb;
                ldsm_x4(b[j], Bb + SWZ(byte));
            }
            #pragma unroll
            for (int i = 0; i < 4; i++)
                #pragma unroll
                for (int j = 0; j < 4; j++) {
                    mma16816(c[i][2 * j],     a[i], b[j][0], b[j][1]);
                    mma16816(c[i][2 * j + 1], a[i], b[j][2], b[j][3]);
                }
        }
    }

    // epilogue
    if (!split) {
        #pragma unroll
        for (int i = 0; i < 4; i++) {
            int r0 = m0 + wm + i * 16 + g;
            #pragma unroll
            for (int j = 0; j < 8; j++) {
                int col = n0 + wn + j * 8 + 2 * q;
                float b0 = bias[col], b1 = bias[col + 1];
                if (r0 < Mdim) {
                    float* d = od + (size_t)r0 * CH + col;
                    d[0] = c[i][j][0] + b0;
                    d[1] = c[i][j][1] + b1;
                }
                if (r0 + 8 < Mdim) {
                    float* d = od + (size_t)(r0 + 8) * CH + col;
                    d[0] = c[i][j][2] + b0;
                    d[1] = c[i][j][3] + b1;
                }
            }
        }
    } else {
        int sel = n0 / CH;
        int cs  = sel * CH;
        __half* outp = (sel == 0) ? oq : (sel == 1 ? ok : ov);
        #pragma unroll
        for (int i = 0; i < 4; i++) {
            int r0 = m0 + wm + i * 16 + g;
            #pragma unroll
            for (int j = 0; j < 8; j++) {
                int col = n0 + wn + j * 8 + 2 * q;
                float b0 = bias[col], b1 = bias[col + 1];
                if (r0 < Mdim) {
                    __half2* d = (__half2*)(outp + (size_t)r0 * CH + (col - cs));
                    *d = __floats2half2_rn(c[i][j][0] + b0, c[i][j][1] + b1);
                }
                if (r0 + 8 < Mdim) {
                    __half2* d = (__half2*)(outp + (size_t)(r0 + 8) * CH + (col - cs));
                    *d = __floats2half2_rn(c[i][j][2] + b0, c[i][j][3] + b1);
                }
            }
        }
    }
}

// ---------------- RMSNorm (fp16, in place, uint4 loads, register-cached) ----------------
__device__ __forceinline__ float sumsq8(uint4 u) {
    float2 a = __half22float2(*reinterpret_cast<__half2*>(&u.x));
    float2 b = __half22float2(*reinterpret_cast<__half2*>(&u.y));
    float2 c = __half22float2(*reinterpret_cast<__half2*>(&u.z));
    float2 d = __half22float2(*reinterpret_cast<__half2*>(&u.w));
    return a.x * a.x + a.y * a.y + b.x * b.x + b.y * b.y +
           c.x * c.x + c.y * c.y + d.x * d.x + d.y * d.y;
}
__device__ __forceinline__ uint4 scale8(uint4 u, float4 w0, float4 w1, float rms) {
    float2 a = __half22float2(*reinterpret_cast<__half2*>(&u.x));
    float2 b = __half22float2(*reinterpret_cast<__half2*>(&u.y));
    float2 c = __half22float2(*reinterpret_cast<__half2*>(&u.z));
    float2 d = __half22float2(*reinterpret_cast<__half2*>(&u.w));
    __half2 h0 = __floats2half2_rn(a.x * rms * w0.x, a.y * rms * w0.y);
    __half2 h1 = __floats2half2_rn(b.x * rms * w0.z, b.y * rms * w0.w);
    __half2 h2 = __floats2half2_rn(c.x * rms * w1.x, c.y * rms * w1.y);
    __half2 h3 = __floats2half2_rn(d.x * rms * w1.z, d.y * rms * w1.w);
    uint4 r;
    r.x = *reinterpret_cast<uint32_t*>(&h0);
    r.y = *reinterpret_cast<uint32_t*>(&h1);
    r.z = *reinterpret_cast<uint32_t*>(&h2);
    r.w = *reinterpret_cast<uint32_t*>(&h3);
    return r;
}

__global__ void rmsnorm_kernel(__half* __restrict__ qbuf, __half* __restrict__ kbuf,
                               const float* __restrict__ qw, const float* __restrict__ kw)
{
    __half* buf    = blockIdx.y ? kbuf : qbuf;
    const float* w = blockIdx.y ? kw : qw;
    const float post = blockIdx.y ? 1.f : 0.08838834764831845f;   // q: fold attn scale
    const size_t row = blockIdx.x;
    uint4* p = (uint4*)(buf + row * CH);          // 400 uint4 per row
    const float4* wp = (const float4*)w;
    const int tid = threadIdx.x;                  // 256

    const bool has1 = (tid + 256) < 400;
    uint4 v0 = p[tid];
    uint4 v1;
    if (has1) v1 = p[tid + 256];

    float ss = sumsq8(v0) + (has1 ? sumsq8(v1) : 0.f);
    __shared__ float red[8];
    #pragma unroll
    for (int off = 16; off > 0; off >>= 1) ss += __shfl_xor_sync(0xffffffffu, ss, off);
    if ((tid & 31) == 0) red[tid >> 5] = ss;
    __syncthreads();
    float tot = 0.f;
    #pragma unroll
    for (int i = 0; i < 8; i++) tot += red[i];
    const float rms = rsqrtf(tot * (1.f / CH) + EPS) * post;

    p[tid] = scale8(v0, wp[2 * tid], wp[2 * tid + 1], rms);
    if (has1) p[tid + 256] = scale8(v1, wp[2 * (tid + 256)], wp[2 * (tid + 256) + 1], rms);
}

// ---------------- flash attention, fp16 mma, register-resident P ----------------
// grid (200, 9): y in [0,8) -> full 128-row q tiles; y == 8 -> scalar tail (row 1024),
// fused in-kernel so its 200 light blocks overlap the 1600 main blocks.
#define ROWB 272
#define AQ_BYTES (128*ROWB)
#define KV_BYTES (2*64*ROWB)
#define ATTN_SMEM (AQ_BYTES + 2*KV_BYTES)  // 104448

__global__ void __launch_bounds__(256, 2) attn_kernel(
    const __half* __restrict__ Q, const __half* __restrict__ K,
    const __half* __restrict__ V, __half* __restrict__ O)
{
    extern __shared__ char smg[];
    const uint32_t sb = smem_u32(smg);
    const int tid  = threadIdx.x;
    const int lane = tid & 31;
    const int wid  = tid >> 5;
    const int g    = lane >> 2;
    const int q    = lane & 3;
    const int bh   = blockIdx.x;
    const int b    = bh / NH;
    const int h    = bh % NH;
    const size_t rowBase = (size_t)b * SEQ;

    if (blockIdx.y == 8) {
        // ===== tail: q row 1024, fp32, smem-staged coalesced K/V =====
        float* qs   = (float*)smg;                 // 128 f
        float* ps   = (float*)(smg + 512);         // 1025 f (ends 4612)
        float* red  = (float*)(smg + 5120);        // 8 f
        float* osum = (float*)(smg + 5184);        // 128 f
        char*  ks   = smg + 5760;                  // 256 rows x 272B = 69632B
        const int qrow = SEQ - 1;

        if (tid < 64) {
            __half2 v = ((const __half2*)(Q + (rowBase + qrow) * (size_t)CH + h * HD))[tid];
            float2 f = __half22float2(v);
            qs[2 * tid] = f.x; qs[2 * tid + 1] = f.y;
        }
        __syncthreads();

        float lmax = -1e30f;
        for (int ck = 0; ck < 5; ck++) {
            const int base = ck * 256;
            const int nrows = min(256, SEQ - base);
            for (int idx = tid; idx < nrows * 16; idx += 256) {
                int r = idx >> 4, c4 = idx & 15;
                const uint4* src = (const uint4*)(K + (rowBase + base + r) * (size_t)CH + h * HD) + c4;
                *(uint4*)(ks + r * 272 + c4 * 16) = *src;
            }
            __syncthreads();
            if (tid < nrows) {
                const uint4* row = (const uint4*)(ks + tid * 272);
                float s = 0.f;
                #pragma unroll
                for (int j = 0; j < 16; j++) {
                    uint4 u = row[j];
                    float2 a  = __half22float2(*reinterpret_cast<__half2*>(&u.x));
                    float2 bb = __half22float2(*reinterpret_cast<__half2*>(&u.y));
                    float2 cc = __half22float2(*reinterpret_cast<__half2*>(&u.z));
                    float2 dd = __half22float2(*reinterpret_cast<__half2*>(&u.w));
                    const float* qp = qs + j * 8;
                    s += a.x * qp[0] + a.y * qp[1] + bb.x * qp[2] + bb.y * qp[3]
                       + cc.x * qp[4] + cc.y * qp[5] + dd.x * qp[6] + dd.y * qp[7];
                }
                ps[base + tid] = s;
                lmax = fmaxf(lmax, s);
            }
            __syncthreads();
        }
        #pragma unroll
        for (int off = 16; off > 0; off >>= 1)
            lmax = fmaxf(lmax, __shfl_xor_sync(0xffffffffu, lmax, off));
        if ((tid & 31) == 0) red[tid >> 5] = lmax;
        __syncthreads();
        float gmax = red[0];
        #pragma unroll
        for (int i = 1; i < 8; i++) gmax = fmaxf(gmax, red[i]);
        __syncthreads();

        float lsum = 0.f;
        for (int k = tid; k < SEQ; k += 256) {
            float p = __expf(ps[k] - gmax);
            ps[k] = p;
            lsum += p;
        }
        #pragma unroll
        for (int off = 16; off > 0; off >>= 1) lsum += __shfl_xor_sync(0xffffffffu, lsum, off);
        if ((tid & 31) == 0) red[tid >> 5] = lsum;
        __syncthreads();
        float gsum = 0.f;
        #pragma unroll
        for (int i = 0; i < 8; i++) gsum += red[i];

        const int d = tid & 127, grp = tid >> 7;
        float acc = 0.f;
        for (int ck = 0; ck < 5; ck++) {
            const int base = ck * 256;
            const int nrows = min(256, SEQ - base);
            __syncthreads();   // prior chunk fully consumed / ps settled
            for (int idx = tid; idx < nrows * 16; idx += 256) {
                int r = idx >> 4, c4 = idx & 15;
                const uint4* src = (const uint4*)(V + (rowBase + base + r) * (size_t)CH + h * HD) + c4;
                *(uint4*)(ks + r * 272 + c4 * 16) = *src;
            }
            __syncthreads();
            for (int r = grp; r < nrows; r += 2)
                acc += ps[base + r] * __half2float(*(__half*)(ks + r * 272 + d * 2));
        }
        if (grp == 0) osum[d] = acc;
        __syncthreads();
        if (grp == 1) osum[d] += acc;
        __syncthreads();
        if (tid < HD)
            O[(rowBase + qrow) * (size_t)CH + h * HD + tid] = __float2half_rn(osum[tid] / gsum);
        return;
    }

    // ===== main path: full 128-row q tile =====
    const int q0 = blockIdx.y * 128;
    const int nkt = (SEQ + 63) / 64;     // 17

    for (int i = tid; i < 2048; i += 256) {
        int r = i >> 4, c = i & 15;
        const __half* src = Q + (rowBase + q0 + r) * (size_t)CH + h * HD + c * 8;
        cp_async16u(sb + r * ROWB + c * 16, src);
    }
    cp_commit();

    auto kvstage = [&](int kt) {
        const int k0 = kt * 64;
        const uint32_t bufb = sb + AQ_BYTES + (kt & 1) * KV_BYTES;
        for (int i = tid; i < 1024; i += 256) {
            int r = i >> 4, c = i & 15;
            int krow = k0 + r;
            size_t off = (rowBase + krow) * (size_t)CH + h * HD + c * 8;
            int ok = krow < SEQ ? 16 : 0;
            cp_async16(bufb + r * ROWB + c * 16, K + off, ok);
            cp_async16(bufb + 64 * ROWB + r * ROWB + c * 16, V + off, ok);
        }
        cp_commit();
    };

    kvstage(0);

    if (tid < 128) {
        int buf = tid >> 6, r = tid & 63;
        uint4* p = (uint4*)(smg + AQ_BYTES + buf * KV_BYTES + 64 * ROWB + r * ROWB + 256);
        *p = make_uint4(0x00003c00u, 0u, 0u, 0u);   // halves {1,0,0,0,0,0,0,0}
    }

    float o[17][4];
    #pragma unroll
    for (int j = 0; j < 17; j++)
        #pragma unroll
        for (int t = 0; t < 4; t++) o[j][t] = 0.f;
    float mstat0 = -1e30f, mstat1 = -1e30f;

    const uint32_t aQbase = sb + (wid * 16 + (lane & 15)) * ROWB + ((lane >> 4) << 4);
    const int bRowOff = (lane & 7) + ((lane & 16) >> 1);
    const int bKb     = (lane & 8) << 1;
    const int vRowOff = ((lane >> 3) & 1) * 8 + (lane & 7);
    const int vColOff = (lane >> 4) << 4;

    for (int kt = 0; kt < nkt; kt++) {
        if (kt + 1 < nkt) kvstage(kt + 1);
        else cp_commit();
        cp_wait1();
        __syncthreads();

        const uint32_t Kb = sb + AQ_BYTES + (kt & 1) * KV_BYTES;
        const uint32_t Vb = Kb + 64 * ROWB;

        float s[8][4];
        #pragma unroll
        for (int nt = 0; nt < 8; nt++)
            #pragma unroll
            for (int t = 0; t < 4; t++) s[nt][t] = 0.f;
        #pragma unroll
        for (int kb = 0; kb < 8; kb++) {
            uint32_t a[4];
            ldsm_x4(a, aQbase + kb * 32);
            #pragma unroll
            for (int nt = 0; nt < 4; nt++) {
                uint32_t bf[4];
                ldsm_x4(bf, Kb + (nt * 16 + bRowOff) * ROWB + kb * 32 + bKb);
                mma16816(s[2 * nt],     a, bf[0], bf[1]);
                mma16816(s[2 * nt + 1], a, bf[2], bf[3]);
            }
        }

        const int kvalid = SEQ - kt * 64;
        if (kvalid < 64) {
            #pragma unroll
            for (int nt = 0; nt < 8; nt++) {
                int colb = nt * 8 + 2 * q;
                if (colb >= kvalid)     { s[nt][0] = -1e30f; s[nt][2] = -1e30f; }
                if (colb + 1 >= kvalid) { s[nt][1] = -1e30f; s[nt][3] = -1e30f; }
            }
        }

        float cm0 = -1e30f, cm1 = -1e30f;
        #pragma unroll
        for (int nt = 0; nt < 8; nt++) {
            cm0 = fmaxf(cm0, fmaxf(s[nt][0], s[nt][1]));
            cm1 = fmaxf(cm1, fmaxf(s[nt][2], s[nt][3]));
        }
        cm0 = fmaxf(cm0, __shfl_xor_sync(0xffffffffu, cm0, 1));
        cm0 = fmaxf(cm0, __shfl_xor_sync(0xffffffffu, cm0, 2));
        cm1 = fmaxf(cm1, __shfl_xor_sync(0xffffffffu, cm1, 1));
        cm1 = fmaxf(cm1, __shfl_xor_sync(0xffffffffu, cm1, 2));

        const float mn0 = fmaxf(mstat0, cm0);
        const float mn1 = fmaxf(mstat1, cm1);
        const float al0 = __expf(mstat0 - mn0);
        const float al1 = __expf(mstat1 - mn1);
        mstat0 = mn0; mstat1 = mn1;
        const float cc0 = -mn0 * LOG2E;
        const float cc1 = -mn1 * LOG2E;

        uint32_t ph[8][2];
        #pragma unroll
        for (int nt = 0; nt < 8; nt++) {
            ph[nt][0] = ex2_h2(pack_h2(fmaf(s[nt][0], LOG2E, cc0),
                                       fmaf(s[nt][1], LOG2E, cc0)));
            ph[nt][1] = ex2_h2(pack_h2(fmaf(s[nt][2], LOG2E, cc1),
                                       fmaf(s[nt][3], LOG2E, cc1)));
        }

        if (__float_as_uint(al0) != 0x3f800000u || __float_as_uint(al1) != 0x3f800000u) {
            #pragma unroll
            for (int j = 0; j < 17; j++) {
                o[j][0] *= al0; o[j][1] *= al0;
                o[j][2] *= al1; o[j][3] *= al1;
            }
        }

        #pragma unroll
        for (int m = 0; m < 4; m++) {
            uint32_t a[4] = { ph[2 * m][0], ph[2 * m][1], ph[2 * m + 1][0], ph[2 * m + 1][1] };
            const uint32_t vb = Vb + (m * 16 + vRowOff) * ROWB;
            #pragma unroll
            for (int nb = 0; nb < 8; nb++) {
                uint32_t r[4];
                ldsm_x4t(r, vb + nb * 32 + vColOff);
                mma16816(o[2 * nb],     a, r[0], r[1]);
                mma16816(o[2 * nb + 1], a, r[2], r[3]);
            }
            uint32_t rl[2];
            ldsm_x2t(rl, Vb + (m * 16 + vRowOff) * ROWB + 256);
            mma16816(o[16], a, rl[0], rl[1]);
        }
        __syncthreads();
    }

    const float l0 = __shfl_sync(0xffffffffu, o[16][0], lane & ~3);
    const float l1 = __shfl_sync(0xffffffffu, o[16][2], lane & ~3);
    const float inv0 = 1.f / l0;
    const float inv1 = 1.f / l1;
    const int row0 = q0 + wid * 16 + g;
    #pragma unroll
    for (int j = 0; j < 16; j++) {
        int col = h * HD + j * 8 + 2 * q;
        __half2* d0 = (__half2*)(O + (rowBase + row0) * (size_t)CH + col);
        *d0 = __floats2half2_rn(o[j][0] * inv0, o[j][1] * inv0);
        __half2* d1 = (__half2*)(O + (rowBase + row0 + 8) * (size_t)CH + col);
        *d1 = __floats2half2_rn(o[j][2] * inv1, o[j][3] * inv1);
    }
}

// ---------------- launch ----------------
extern "C" void kernel_launch(void* const* d_in, const int* in_sizes, int n_in,
                              void* d_out, int out_size)
{
    const float* x     = (const float*)d_in[0];
    const float* qkvW  = (const float*)d_in[1];
    const float* qkvB  = (const float*)d_in[2];
    const float* qNW   = (const float*)d_in[3];
    const float* kNW   = (const float*)d_in[4];
    const float* projW = (const float*)d_in[5];
    const float* projB = (const float*)d_in[6];
    float* out = (float*)d_out;

    __half *pxh, *pwqT, *pwpT, *pqh, *pkh, *pvh, *po;
    cudaGetSymbolAddress((void**)&pxh,  g_xh);
    cudaGetSymbolAddress((void**)&pwqT, g_wqkvT);
    cudaGetSymbolAddress((void**)&pwpT, g_wprojT);
    cudaGetSymbolAddress((void**)&pqh,  g_qh);
    cudaGetSymbolAddress((void**)&pkh,  g_kh);
    cudaGetSymbolAddress((void**)&pvh,  g_vh);
    cudaGetSymbolAddress((void**)&po,   g_o);

    cudaFuncSetAttribute(hgemm,       cudaFuncAttributeMaxDynamicSharedMemorySize, HG_SMEM);
    cudaFuncSetAttribute(attn_kernel, cudaFuncAttributeMaxDynamicSharedMemorySize, ATTN_SMEM);

    const int n1 = MROWS * CH;
    f2h_kernel<<<(n1 / 4 + 255) / 256, 256>>>((const float4*)x, (uint2*)pxh, n1 / 4);
    transpose2_h<<<dim3(400, 100), dim3(32, 8)>>>(qkvW, pwqT, projW, pwpT);

    // qkv = x @ W_qkv + b  ->  q,k,v fp16
    hgemm<<<dim3(65, 75), 128, HG_SMEM>>>(pxh, pwqT, qkvB, pqh, pkh, pvh, nullptr, MROWS, 1);
    // RMSNorm in place (q gets attn scale folded)
    rmsnorm_kernel<<<dim3(MROWS, 2), 256>>>(pqh, pkh, qNW, kNW);
    // flash attention: 8 full q-tiles + fused in-kernel tail for row 1024
    attn_kernel<<<dim3(BATCH * NH, 9), 256, ATTN_SMEM>>>(pqh, pkh, pvh, po);
    // out = attn_out @ W_proj + b (fp32 out)
    hgemm<<<dim3(65, 25), 128, HG_SMEM>>>(po, pwpT, projB, nullptr, nullptr, nullptr, out, MROWS, 0);
}

// round 15
// speedup vs baseline: 1.1019x; 1.0107x over previous
#include <cuda_runtime.h>
#include <cuda_fp16.h>
#include <cstdint>
#include <cstddef>

// ---------------- problem constants ----------------
#define BATCH 8
#define SEQ   1025
#define CH    3200
#define NH    25
#define HD    128
#define MROWS (BATCH*SEQ)   // 8200
#define EPS   1e-6f
#define LOG2E 1.4426950408889634f

// ---------------- device scratch (no allocation allowed) ----------------
__device__ __half g_xh  [MROWS*CH];      // fp16 x
__device__ __half g_wqkvT[3*CH*CH];      // fp16, TRANSPOSED qkv weights [3C, C]
__device__ __half g_wprojT[CH*CH];       // fp16, TRANSPOSED proj weights [C, C]
__device__ __half g_qh  [MROWS*CH];      // fp16 q (pre-norm -> normalized in place)
__device__ __half g_kh  [MROWS*CH];      // fp16 k (pre-norm -> normalized in place)
__device__ __half g_vh  [MROWS*CH];      // fp16 v
__device__ __half g_o   [MROWS*CH];      // attention output (fp16 for proj GEMM)

// ---------------- PTX helpers ----------------
__device__ __forceinline__ uint32_t smem_u32(const void* p) {
    uint32_t a;
    asm("{ .reg .u64 t; cvta.to.shared.u64 t, %1; cvt.u32.u64 %0, t; }" : "=r"(a) : "l"(p));
    return a;
}

__device__ __forceinline__ void cp_async16(uint32_t smem_addr, const void* gptr, int srcBytes) {
    asm volatile("cp.async.cg.shared.global [%0], [%1], 16, %2;\n"
                 :: "r"(smem_addr), "l"(gptr), "r"(srcBytes) : "memory");
}
__device__ __forceinline__ void cp_async16u(uint32_t smem_addr, const void* gptr) {
    asm volatile("cp.async.cg.shared.global [%0], [%1], 16;\n"
                 :: "r"(smem_addr), "l"(gptr) : "memory");
}
__device__ __forceinline__ void cp_commit() {
    asm volatile("cp.async.commit_group;\n" ::: "memory");
}
__device__ __forceinline__ void cp_wait1() {
    asm volatile("cp.async.wait_group 1;\n" ::: "memory");
}

__device__ __forceinline__ void ldsm_x4(uint32_t r[4], uint32_t addr) {
    asm volatile("ldmatrix.sync.aligned.m8n8.x4.shared.b16 {%0,%1,%2,%3}, [%4];"
                 : "=r"(r[0]), "=r"(r[1]), "=r"(r[2]), "=r"(r[3]) : "r"(addr));
}
__device__ __forceinline__ void ldsm_x4t(uint32_t r[4], uint32_t addr) {
    asm volatile("ldmatrix.sync.aligned.m8n8.x4.trans.shared.b16 {%0,%1,%2,%3}, [%4];"
                 : "=r"(r[0]), "=r"(r[1]), "=r"(r[2]), "=r"(r[3]) : "r"(addr));
}
__device__ __forceinline__ void ldsm_x2t(uint32_t r[2], uint32_t addr) {
    asm volatile("ldmatrix.sync.aligned.m8n8.x2.trans.shared.b16 {%0,%1}, [%2];"
                 : "=r"(r[0]), "=r"(r[1]) : "r"(addr));
}

__device__ __forceinline__ void mma16816(float c[4], const uint32_t a[4],
                                         uint32_t b0, uint32_t b1) {
    asm volatile(
        "mma.sync.aligned.m16n8k16.row.col.f32.f16.f16.f32 "
        "{%0,%1,%2,%3}, {%4,%5,%6,%7}, {%8,%9}, {%0,%1,%2,%3};\n"
        : "+f"(c[0]), "+f"(c[1]), "+f"(c[2]), "+f"(c[3])
        : "r"(a[0]), "r"(a[1]), "r"(a[2]), "r"(a[3]), "r"(b0), "r"(b1));
}

__device__ __forceinline__ uint32_t ex2_h2(uint32_t x) {
    uint32_t r;
    asm volatile("ex2.approx.f16x2 %0, %1;" : "=r"(r) : "r"(x));
    return r;
}

__device__ __forceinline__ uint32_t pack_h2(float lo, float hi) {
    __half2 h = __floats2half2_rn(lo, hi);
    return *reinterpret_cast<uint32_t*>(&h);
}

#define SWZ(b) ((b) ^ (((b) >> 3) & 0x70))

// ---------------- fused prep: f2h(x) + transpose both weight matrices ----------------
#define F2H_NBLK 25625          // MROWS*CH/4/256 exactly
#define TR_QKV_NX 300           // 3*CH/32
#define TR_NX     400
__global__ void prep_kernel(const float4* __restrict__ x, uint2* __restrict__ xh,
                            const float* __restrict__ w1, __half* __restrict__ o1,
                            const float* __restrict__ w2, __half* __restrict__ o2)
{
    __shared__ float t[32][33];
    const int tid = threadIdx.x;
    if (blockIdx.x < F2H_NBLK) {
        int i = blockIdx.x * 256 + tid;
        float4 v = x[i];
        __half2 lo = __floats2half2_rn(v.x, v.y);
        __half2 hi = __floats2half2_rn(v.z, v.w);
        uint2 u;
        u.x = *reinterpret_cast<uint32_t*>(&lo);
        u.y = *reinterpret_cast<uint32_t*>(&hi);
        xh[i] = u;
        return;
    }
    int bid = blockIdx.x - F2H_NBLK;
    int bx = bid % TR_NX, by = bid / TR_NX;
    const float* in;
    __half* out;
    int N;
    if (bx < TR_QKV_NX) { in = w1; out = o1; N = 3 * CH; }
    else                { in = w2; out = o2; N = CH; bx -= TR_QKV_NX; }
    const int nb = bx * 32, kb = by * 32;
    const int tx = tid & 31, ty = tid >> 5;
    #pragma unroll
    for (int j = 0; j < 32; j += 8)
        t[ty + j][tx] = in[(size_t)(kb + ty + j) * N + nb + tx];
    __syncthreads();
    #pragma unroll
    for (int j = 0; j < 32; j += 8)
        out[(size_t)(nb + ty + j) * CH + kb + tx] = __float2half_rn(t[tx][ty + j]);
}

// ---------------- fp16 GEMM: 128x128 CTA tile, 4 warps x (64x64), 2 CTA/SM ----------------
#define HSTG 32768
#define HG_SMEM (3*HSTG)

__global__ void __launch_bounds__(128, 2) hgemm(
    const __half* __restrict__ A, const __half* __restrict__ BT,
    const float* __restrict__ bias,
    __half* __restrict__ oq, __half* __restrict__ ok, __half* __restrict__ ov,
    float* __restrict__ od,
    int Mdim, int split)
{
    extern __shared__ char smg[];
    const uint32_t sb = smem_u32(smg);
    const int tid  = threadIdx.x;
    const int lane = tid & 31;
    const int wid  = tid >> 5;          // 0..3
    const int g    = lane >> 2;
    const int q    = lane & 3;
    const int m0   = blockIdx.x * 128;
    const int n0   = blockIdx.y * 128;
    const int wm   = (wid & 1) * 64;
    const int wn   = (wid >> 1) * 64;
    const int nk   = CH / 64;           // 50
    const bool fullM = (m0 + 128 <= Mdim);

    float c[4][8][4];
    #pragma unroll
    for (int i = 0; i < 4; i++)
        #pragma unroll
        for (int j = 0; j < 8; j++)
            #pragma unroll
            for (int t = 0; t < 4; t++) c[i][j][t] = 0.f;

    const int ldR = tid >> 3, ldC = tid & 7;

    auto stage = [&](int ts) {
        const int k0 = ts * 64;
        const uint32_t bufb = sb + (ts % 3) * HSTG;
        if (fullM) {
            #pragma unroll
            for (int i = 0; i < 8; i++) {
                int r = ldR + (i << 4);
                const __half* src = A + (size_t)(m0 + r) * CH + k0 + ldC * 8;
                uint32_t byte = (r << 7) + (ldC << 4);
                cp_async16u(bufb + SWZ(byte), src);
            }
        } else {
            #pragma unroll
            for (int i = 0; i < 8; i++) {
                int r = ldR + (i << 4);
                int grow = m0 + r;
                const __half* src = A + (size_t)(grow < Mdim ? grow : 0) * CH + k0 + ldC * 8;
                uint32_t byte = (r << 7) + (ldC << 4);
                cp_async16(bufb + SWZ(byte), src, grow < Mdim ? 16 : 0);
            }
        }
        #pragma unroll
        for (int i = 0; i < 8; i++) {
            int r = ldR + (i << 4);
            const __half* src = BT + (size_t)(n0 + r) * CH + k0 + ldC * 8;
            uint32_t byte = (r << 7) + (ldC << 4);
            cp_async16u(bufb + 16384 + SWZ(byte), src);
        }
        cp_commit();
    };

    stage(0);
    stage(1);

    const int aRow = wm + (lane & 15);
    const int aKb  = (lane >> 4) << 4;
    const int bRow = wn + (lane & 7) + ((lane & 16) >> 1);
    const int bKb  = (lane & 8) << 1;

    for (int kt = 0; kt < nk; kt++) {
        cp_wait1();
        __syncthreads();
        if (kt + 2 < nk) stage(kt + 2);
        else cp_commit();

        const uint32_t Ab = sb + (kt % 3) * HSTG;
        const uint32_t Bb = Ab + 16384;
        #pragma unroll
        for (int ks = 0; ks < 4; ks++) {
            uint32_t a[4][4], b[4][4];
            #pragma unroll
            for (int i = 0; i < 4; i++) {
                uint32_t byte = ((aRow + i * 16) << 7) + ks * 32 + aKb;
                ldsm_x4(a[i], Ab + SWZ(byte));
            }
            #pragma unroll
            for (int j = 0; j < 4; j++) {
                uint32_t byte = ((bRow + j * 16) << 7) + ks * 32 + bKb;
                ldsm_x4(b[j], Bb + SWZ(byte));
            }
            #pragma unroll
            for (int i = 0; i < 4; i++)
                #pragma unroll
                for (int j = 0; j < 4; j++) {
                    mma16816(c[i][2 * j],     a[i], b[j][0], b[j][1]);
                    mma16816(c[i][2 * j + 1], a[i], b[j][2], b[j][3]);
                }
        }
    }

    // epilogue
    if (!split) {
        #pragma unroll
        for (int i = 0; i < 4; i++) {
            int r0 = m0 + wm + i * 16 + g;
            #pragma unroll
            for (int j = 0; j < 8; j++) {
                int col = n0 + wn + j * 8 + 2 * q;
                float b0 = bias[col], b1 = bias[col + 1];
                if (r0 < Mdim) {
                    float* d = od + (size_t)r0 * CH + col;
                    d[0] = c[i][j][0] + b0;
                    d[1] = c[i][j][1] + b1;
                }
                if (r0 + 8 < Mdim) {
                    float* d = od + (size_t)(r0 + 8) * CH + col;
                    d[0] = c[i][j][2] + b0;
                    d[1] = c[i][j][3] + b1;
                }
            }
        }
    } else {
        int sel = n0 / CH;
        int cs  = sel * CH;
        __half* outp = (sel == 0) ? oq : (sel == 1 ? ok : ov);
        #pragma unroll
        for (int i = 0; i < 4; i++) {
            int r0 = m0 + wm + i * 16 + g;
            #pragma unroll
            for (int j = 0; j < 8; j++) {
                int col = n0 + wn + j * 8 + 2 * q;
                float b0 = bias[col], b1 = bias[col + 1];
                if (r0 < Mdim) {
                    __half2* d = (__half2*)(outp + (size_t)r0 * CH + (col - cs));
                    *d = __floats2half2_rn(c[i][j][0] + b0, c[i][j][1] + b1);
                }
                if (r0 + 8 < Mdim) {
                    __half2* d = (__half2*)(outp + (size_t)(r0 + 8) * CH + (col - cs));
                    *d = __floats2half2_rn(c[i][j][2] + b0, c[i][j][3] + b1);
                }
            }
        }
    }
}

// ---------------- RMSNorm (fp16, in place, uint4 loads, register-cached) ----------------
__device__ __forceinline__ float sumsq8(uint4 u) {
    float2 a = __half22float2(*reinterpret_cast<__half2*>(&u.x));
    float2 b = __half22float2(*reinterpret_cast<__half2*>(&u.y));
    float2 c = __half22float2(*reinterpret_cast<__half2*>(&u.z));
    float2 d = __half22float2(*reinterpret_cast<__half2*>(&u.w));
    return a.x * a.x + a.y * a.y + b.x * b.x + b.y * b.y +
           c.x * c.x + c.y * c.y + d.x * d.x + d.y * d.y;
}
__device__ __forceinline__ uint4 scale8(uint4 u, float4 w0, float4 w1, float rms) {
    float2 a = __half22float2(*reinterpret_cast<__half2*>(&u.x));
    float2 b = __half22float2(*reinterpret_cast<__half2*>(&u.y));
    float2 c = __half22float2(*reinterpret_cast<__half2*>(&u.z));
    float2 d = __half22float2(*reinterpret_cast<__half2*>(&u.w));
    __half2 h0 = __floats2half2_rn(a.x * rms * w0.x, a.y * rms * w0.y);
    __half2 h1 = __floats2half2_rn(b.x * rms * w0.z, b.y * rms * w0.w);
    __half2 h2 = __floats2half2_rn(c.x * rms * w1.x, c.y * rms * w1.y);
    __half2 h3 = __floats2half2_rn(d.x * rms * w1.z, d.y * rms * w1.w);
    uint4 r;
    r.x = *reinterpret_cast<uint32_t*>(&h0);
    r.y = *reinterpret_cast<uint32_t*>(&h1);
    r.z = *reinterpret_cast<uint32_t*>(&h2);
    r.w = *reinterpret_cast<uint32_t*>(&h3);
    return r;
}

__global__ void rmsnorm_kernel(__half* __restrict__ qbuf, __half* __restrict__ kbuf,
                               const float* __restrict__ qw, const float* __restrict__ kw)
{
    __half* buf    = blockIdx.y ? kbuf : qbuf;
    const float* w = blockIdx.y ? kw : qw;
    const float post = blockIdx.y ? 1.f : 0.08838834764831845f;   // q: fold attn scale
    const size_t row = blockIdx.x;
    uint4* p = (uint4*)(buf + row * CH);          // 400 uint4 per row
    const float4* wp = (const float4*)w;
    const int tid = threadIdx.x;                  // 256

    const bool has1 = (tid + 256) < 400;
    uint4 v0 = p[tid];
    uint4 v1;
    if (has1) v1 = p[tid + 256];

    float ss = sumsq8(v0) + (has1 ? sumsq8(v1) : 0.f);
    __shared__ float red[8];
    #pragma unroll
    for (int off = 16; off > 0; off >>= 1) ss += __shfl_xor_sync(0xffffffffu, ss, off);
    if ((tid & 31) == 0) red[tid >> 5] = ss;
    __syncthreads();
    float tot = 0.f;
    #pragma unroll
    for (int i = 0; i < 8; i++) tot += red[i];
    const float rms = rsqrtf(tot * (1.f / CH) + EPS) * post;

    p[tid] = scale8(v0, wp[2 * tid], wp[2 * tid + 1], rms);
    if (has1) p[tid + 256] = scale8(v1, wp[2 * (tid + 256)], wp[2 * (tid + 256) + 1], rms);
}

// ---------------- flash attention, fp16 mma, register-resident P ----------------
// grid (200, 9): y in [0,8) -> full 128-row q tiles over keys [0,1024) in 16 FULL
// KV tiles + scalar update for key 1024; y == 8 -> scalar tail for q row 1024.
#define ROWB 272
#define AQ_BYTES (128*ROWB)
#define KV_BYTES (2*64*ROWB)
#define ATTN_SMEM (AQ_BYTES + 2*KV_BYTES)  // 104448

__global__ void __launch_bounds__(256, 2) attn_kernel(
    const __half* __restrict__ Q, const __half* __restrict__ K,
    const __half* __restrict__ V, __half* __restrict__ O)
{
    extern __shared__ char smg[];
    const uint32_t sb = smem_u32(smg);
    const int tid  = threadIdx.x;
    const int lane = tid & 31;
    const int wid  = tid >> 5;
    const int g    = lane >> 2;
    const int q    = lane & 3;
    const int bh   = blockIdx.x;
    const int b    = bh / NH;
    const int h    = bh % NH;
    const size_t rowBase = (size_t)b * SEQ;

    if (blockIdx.y == 8) {
        // ===== tail: q row 1024, fp32, smem-staged coalesced K/V =====
        float* qs   = (float*)smg;                 // 128 f
        float* ps   = (float*)(smg + 512);         // 1025 f
        float* red  = (float*)(smg + 5120);        // 8 f
        float* osum = (float*)(smg + 5184);        // 128 f
        char*  ks   = smg + 5760;                  // 256 rows x 272B
        const int qrow = SEQ - 1;

        if (tid < 64) {
            __half2 v = ((const __half2*)(Q + (rowBase + qrow) * (size_t)CH + h * HD))[tid];
            float2 f = __half22float2(v);
            qs[2 * tid] = f.x; qs[2 * tid + 1] = f.y;
        }
        __syncthreads();

        float lmax = -1e30f;
        for (int ck = 0; ck < 5; ck++) {
            const int base = ck * 256;
            const int nrows = min(256, SEQ - base);
            for (int idx = tid; idx < nrows * 16; idx += 256) {
                int r = idx >> 4, c4 = idx & 15;
                const uint4* src = (const uint4*)(K + (rowBase + base + r) * (size_t)CH + h * HD) + c4;
                *(uint4*)(ks + r * 272 + c4 * 16) = *src;
            }
            __syncthreads();
            if (tid < nrows) {
                const uint4* row = (const uint4*)(ks + tid * 272);
                float s = 0.f;
                #pragma unroll
                for (int j = 0; j < 16; j++) {
                    uint4 u = row[j];
                    float2 a  = __half22float2(*reinterpret_cast<__half2*>(&u.x));
                    float2 bb = __half22float2(*reinterpret_cast<__half2*>(&u.y));
                    float2 cc = __half22float2(*reinterpret_cast<__half2*>(&u.z));
                    float2 dd = __half22float2(*reinterpret_cast<__half2*>(&u.w));
                    const float* qp = qs + j * 8;
                    s += a.x * qp[0] + a.y * qp[1] + bb.x * qp[2] + bb.y * qp[3]
                       + cc.x * qp[4] + cc.y * qp[5] + dd.x * qp[6] + dd.y * qp[7];
                }
                ps[base + tid] = s;
                lmax = fmaxf(lmax, s);
            }
            __syncthreads();
        }
        #pragma unroll
        for (int off = 16; off > 0; off >>= 1)
            lmax = fmaxf(lmax, __shfl_xor_sync(0xffffffffu, lmax, off));
        if ((tid & 31) == 0) red[tid >> 5] = lmax;
        __syncthreads();
        float gmax = red[0];
        #pragma unroll
        for (int i = 1; i < 8; i++) gmax = fmaxf(gmax, red[i]);
        __syncthreads();

        float lsum = 0.f;
        for (int k = tid; k < SEQ; k += 256) {
            float p = __expf(ps[k] - gmax);
            ps[k] = p;
            lsum += p;
        }
        #pragma unroll
        for (int off = 16; off > 0; off >>= 1) lsum += __shfl_xor_sync(0xffffffffu, lsum, off);
        if ((tid & 31) == 0) red[tid >> 5] = lsum;
        __syncthreads();
        float gsum = 0.f;
        #pragma unroll
        for (int i = 0; i < 8; i++) gsum += red[i];

        const int d = tid & 127, grp = tid >> 7;
        float acc = 0.f;
        for (int ck = 0; ck < 5; ck++) {
            const int base = ck * 256;
            const int nrows = min(256, SEQ - base);
            __syncthreads();
            for (int idx = tid; idx < nrows * 16; idx += 256) {
                int r = idx >> 4, c4 = idx & 15;
                const uint4* src = (const uint4*)(V + (rowBase + base + r) * (size_t)CH + h * HD) + c4;
                *(uint4*)(ks + r * 272 + c4 * 16) = *src;
            }
            __syncthreads();
            for (int r = grp; r < nrows; r += 2)
                acc += ps[base + r] * __half2float(*(__half*)(ks + r * 272 + d * 2));
        }
        if (grp == 0) osum[d] = acc;
        __syncthreads();
        if (grp == 1) osum[d] += acc;
        __syncthreads();
        if (tid < HD)
            O[(rowBase + qrow) * (size_t)CH + h * HD + tid] = __float2half_rn(osum[tid] / gsum);
        return;
    }

    // ===== main path: full 128-row q tile, 16 full KV tiles (keys 0..1023) =====
    const int q0 = blockIdx.y * 128;
    const int nkt = 16;

    for (int i = tid; i < 2048; i += 256) {
        int r = i >> 4, c = i & 15;
        const __half* src = Q + (rowBase + q0 + r) * (size_t)CH + h * HD + c * 8;
        cp_async16u(sb + r * ROWB + c * 16, src);
    }
    cp_commit();

    auto kvstage = [&](int kt) {
        const int k0 = kt * 64;
        const uint32_t bufb = sb + AQ_BYTES + (kt & 1) * KV_BYTES;
        for (int i = tid; i < 1024; i += 256) {
            int r = i >> 4, c = i & 15;
            size_t off = (rowBase + k0 + r) * (size_t)CH + h * HD + c * 8;
            cp_async16u(bufb + r * ROWB + c * 16, K + off);
            cp_async16u(bufb + 64 * ROWB + r * ROWB + c * 16, V + off);
        }
        cp_commit();
    };

    kvstage(0);

    if (tid < 128) {
        int buf = tid >> 6, r = tid & 63;
        uint4* p = (uint4*)(smg + AQ_BYTES + buf * KV_BYTES + 64 * ROWB + r * ROWB + 256);
        *p = make_uint4(0x00003c00u, 0u, 0u, 0u);   // halves {1,0,0,0,0,0,0,0}
    }

    float o[17][4];
    #pragma unroll
    for (int j = 0; j < 17; j++)
        #pragma unroll
        for (int t = 0; t < 4; t++) o[j][t] = 0.f;
    float mstat0 = -1e30f, mstat1 = -1e30f;

    const uint32_t aQbase = sb + (wid * 16 + (lane & 15)) * ROWB + ((lane >> 4) << 4);
    const int bRowOff = (lane & 7) + ((lane & 16) >> 1);
    const int bKb     = (lane & 8) << 1;
    const int vRowOff = ((lane >> 3) & 1) * 8 + (lane & 7);
    const int vColOff = (lane >> 4) << 4;

    for (int kt = 0; kt < nkt; kt++) {
        if (kt + 1 < nkt) kvstage(kt + 1);
        else cp_commit();
        cp_wait1();
        __syncthreads();

        const uint32_t Kb = sb + AQ_BYTES + (kt & 1) * KV_BYTES;
        const uint32_t Vb = Kb + 64 * ROWB;

        float s[8][4];
        #pragma unroll
        for (int nt = 0; nt < 8; nt++)
            #pragma unroll
            for (int t = 0; t < 4; t++) s[nt][t] = 0.f;
        #pragma unroll
        for (int kb = 0; kb < 8; kb++) {
            uint32_t a[4];
            ldsm_x4(a, aQbase + kb * 32);
            #pragma unroll
            for (int nt = 0; nt < 4; nt++) {
                uint32_t bf[4];
                ldsm_x4(bf, Kb + (nt * 16 + bRowOff) * ROWB + kb * 32 + bKb);
                mma16816(s[2 * nt],     a, bf[0], bf[1]);
                mma16816(s[2 * nt + 1], a, bf[2], bf[3]);
            }
        }

        float cm0 = -1e30f, cm1 = -1e30f;
        #pragma unroll
        for (int nt = 0; nt < 8; nt++) {
            cm0 = fmaxf(cm0, fmaxf(s[nt][0], s[nt][1]));
            cm1 = fmaxf(cm1, fmaxf(s[nt][2], s[nt][3]));
        }
        cm0 = fmaxf(cm0, __shfl_xor_sync(0xffffffffu, cm0, 1));
        cm0 = fmaxf(cm0, __shfl_xor_sync(0xffffffffu, cm0, 2));
        cm1 = fmaxf(cm1, __shfl_xor_sync(0xffffffffu, cm1, 1));
        cm1 = fmaxf(cm1, __shfl_xor_sync(0xffffffffu, cm1, 2));

        const float mn0 = fmaxf(mstat0, cm0);
        const float mn1 = fmaxf(mstat1, cm1);
        const float al0 = __expf(mstat0 - mn0);
        const float al1 = __expf(mstat1 - mn1);
        mstat0 = mn0; mstat1 = mn1;
        const float cc0 = -mn0 * LOG2E;
        const float cc1 = -mn1 * LOG2E;

        uint32_t ph[8][2];
        #pragma unroll
        for (int nt = 0; nt < 8; nt++) {
            ph[nt][0] = ex2_h2(pack_h2(fmaf(s[nt][0], LOG2E, cc0),
                                       fmaf(s[nt][1], LOG2E, cc0)));
            ph[nt][1] = ex2_h2(pack_h2(fmaf(s[nt][2], LOG2E, cc1),
                                       fmaf(s[nt][3], LOG2E, cc1)));
        }

        if (__float_as_uint(al0) != 0x3f800000u || __float_as_uint(al1) != 0x3f800000u) {
            #pragma unroll
            for (int j = 0; j < 17; j++) {
                o[j][0] *= al0; o[j][1] *= al0;
                o[j][2] *= al1; o[j][3] *= al1;
            }
        }

        #pragma unroll
        for (int m = 0; m < 4; m++) {
            uint32_t a[4] = { ph[2 * m][0], ph[2 * m][1], ph[2 * m + 1][0], ph[2 * m + 1][1] };
            const uint32_t vb = Vb + (m * 16 + vRowOff) * ROWB;
            #pragma unroll
            for (int nb = 0; nb < 8; nb++) {
                uint32_t r[4];
                ldsm_x4t(r, vb + nb * 32 + vColOff);
                mma16816(o[2 * nb],     a, r[0], r[1]);
                mma16816(o[2 * nb + 1], a, r[2], r[3]);
            }
            uint32_t rl[2];
            ldsm_x2t(rl, Vb + (m * 16 + vRowOff) * ROWB + 256);
            mma16816(o[16], a, rl[0], rl[1]);
        }
        __syncthreads();
    }

    // ===== scalar online-softmax update for key 1024 =====
    {
        __half* kvs = (__half*)(smg + AQ_BYTES);   // KV buffers free now
        const uint4* kp = (const uint4*)(K + (rowBase + 1024) * (size_t)CH + h * HD);
        const uint4* vp = (const uint4*)(V + (rowBase + 1024) * (size_t)CH + h * HD);
        if (tid < 16)       ((uint4*)kvs)[tid] = kp[tid];
        else if (tid < 32)  ((uint4*)kvs)[tid] = vp[tid - 16];   // v at halves [128,256)
        __syncthreads();

        const int r0 = wid * 16 + g;
        const __half2* q0p = (const __half2*)(smg + r0 * ROWB) + q * 16;
        const __half2* q1p = (const __half2*)(smg + (r0 + 8) * ROWB) + q * 16;
        const __half2* kk  = (const __half2*)kvs + q * 16;
        float s0 = 0.f, s1 = 0.f;
        #pragma unroll
        for (int d2 = 0; d2 < 16; d2++) {
            float2 kf = __half22float2(kk[d2]);
            float2 qa = __half22float2(q0p[d2]);
            float2 qb = __half22float2(q1p[d2]);
            s0 += qa.x * kf.x + qa.y * kf.y;
            s1 += qb.x * kf.x + qb.y * kf.y;
        }
        s0 += __shfl_xor_sync(0xffffffffu, s0, 1);
        s0 += __shfl_xor_sync(0xffffffffu, s0, 2);
        s1 += __shfl_xor_sync(0xffffffffu, s1, 1);
        s1 += __shfl_xor_sync(0xffffffffu, s1, 2);

        const float mn0 = fmaxf(mstat0, s0);
        const float mn1 = fmaxf(mstat1, s1);
        const float al0 = __expf(mstat0 - mn0);
        const float al1 = __expf(mstat1 - mn1);
        const float p0  = __expf(s0 - mn0);
        const float p1  = __expf(s1 - mn1);
        if (__float_as_uint(al0) != 0x3f800000u || __float_as_uint(al1) != 0x3f800000u) {
            #pragma unroll
            for (int j = 0; j < 17; j++) {
                o[j][0] *= al0; o[j][1] *= al0;
                o[j][2] *= al1; o[j][3] *= al1;
            }
        }
        const __half* vv = kvs + 128;
        #pragma unroll
        for (int j = 0; j < 16; j++) {
            int col = j * 8 + 2 * q;
            float v0 = __half2float(vv[col]);
            float v1 = __half2float(vv[col + 1]);
            o[j][0] += p0 * v0; o[j][1] += p0 * v1;
            o[j][2] += p1 * v0; o[j][3] += p1 * v1;
        }
        if (q == 0) { o[16][0] += p0; o[16][2] += p1; }
    }

    const float l0 = __shfl_sync(0xffffffffu, o[16][0], lane & ~3);
    const float l1 = __shfl_sync(0xffffffffu, o[16][2], lane & ~3);
    const float inv0 = 1.f / l0;
    const float inv1 = 1.f / l1;
    const int row0 = q0 + wid * 16 + g;
    #pragma unroll
    for (int j = 0; j < 16; j++) {
        int col = h * HD + j * 8 + 2 * q;
        __half2* d0 = (__half2*)(O + (rowBase + row0) * (size_t)CH + col);
        *d0 = __floats2half2_rn(o[j][0] * inv0, o[j][1] * inv0);
        __half2* d1 = (__half2*)(O + (rowBase + row0 + 8) * (size_t)CH + col);
        *d1 = __floats2half2_rn(o[j][2] * inv1, o[j][3] * inv1);
    }
}

// ---------------- launch ----------------
extern "C" void kernel_launch(void* const* d_in, const int* in_sizes, int n_in,
                              void* d_out, int out_size)
{
    const float* x     = (const float*)d_in[0];
    const float* qkvW  = (const float*)d_in[1];
    const float* qkvB  = (const float*)d_in[2];
    const float* qNW   = (const float*)d_in[3];
    const float* kNW   = (const float*)d_in[4];
    const float* projW = (const float*)d_in[5];
    const float* projB = (const float*)d_in[6];
    float* out = (float*)d_out;

    __half *pxh, *pwqT, *pwpT, *pqh, *pkh, *pvh, *po;
    cudaGetSymbolAddress((void**)&pxh,  g_xh);
    cudaGetSymbolAddress((void**)&pwqT, g_wqkvT);
    cudaGetSymbolAddress((void**)&pwpT, g_wprojT);
    cudaGetSymbolAddress((void**)&pqh,  g_qh);
    cudaGetSymbolAddress((void**)&pkh,  g_kh);
    cudaGetSymbolAddress((void**)&pvh,  g_vh);
    cudaGetSymbolAddress((void**)&po,   g_o);

    cudaFuncSetAttribute(hgemm,       cudaFuncAttributeMaxDynamicSharedMemorySize, HG_SMEM);
    cudaFuncSetAttribute(attn_kernel, cudaFuncAttributeMaxDynamicSharedMemorySize, ATTN_SMEM);

    // fused prep: f2h(x) + transposed fp16 weights
    prep_kernel<<<F2H_NBLK + TR_NX * 100, 256>>>((const float4*)x, (uint2*)pxh,
                                                 qkvW, pwqT, projW, pwpT);

    // qkv = x @ W_qkv + b  ->  q,k,v fp16
    hgemm<<<dim3(65, 75), 128, HG_SMEM>>>(pxh, pwqT, qkvB, pqh, pkh, pvh, nullptr, MROWS, 1);
    // RMSNorm in place (q gets attn scale folded)
    rmsnorm_kernel<<<dim3(MROWS, 2), 256>>>(pqh, pkh, qNW, kNW);
    // flash attention: 8 full q-tiles (16 full KV tiles + key-1024 update) + fused tail
    attn_kernel<<<dim3(BATCH * NH, 9), 256, ATTN_SMEM>>>(pqh, pkh, pvh, po);
    // out = attn_out @ W_proj + b (fp32 out)
    hgemm<<<dim3(65, 25), 128, HG_SMEM>>>(po, pwpT, projB, nullptr, nullptr, nullptr, out, MROWS, 0);
}